// round 16
// baseline (speedup 1.0000x reference)
#include <cuda_runtime.h>
#include <cstdint>

#define BATCH 16
#define SEQ   1024
#define CH    768
#define HEADS 12
#define DHEAD 64
#define NTOK  1220              // 1024 + 196
#define NKV   1280              // padded key count
#define MQKV  (BATCH*NTOK)      // 19520 rows of xt
#define QKVN  (3*CH)            // 2304

// ---------------- scratch (zero-initialized). RULE: referenced ONLY in
// device code, never passed as kernel arguments. ----------------------------
__device__ float g_W1[CH*QKVN];                  // W_qkv, tf32-rounded (rna)
__device__ float g_W2[CH*CH];                    // W_proj, tf32-rounded (rna)
__device__ float g_Q [BATCH*HEADS*SEQ *DHEAD];   // tf32-rounded
__device__ float g_K [BATCH*HEADS*NKV *DHEAD];   // tf32-rounded; pad rows 0
__device__ float g_V [BATCH*HEADS*NKV *DHEAD];   // tf32-rounded
__device__ float g_AT[BATCH*SEQ*CH];             // attn out, tf32-rounded

// ---------------- helpers ----------------
__device__ __forceinline__ unsigned f2t(float x){
    unsigned u; asm("cvt.rna.tf32.f32 %0, %1;" : "=r"(u) : "f"(x)); return u;
}
__device__ __forceinline__ float tf32r(float x){
    unsigned u; asm("cvt.rna.tf32.f32 %0, %1;" : "=r"(u) : "f"(x));
    return __uint_as_float(u);
}
__device__ __forceinline__ void mma8(float* c, const unsigned* a, const unsigned* b){
    asm volatile("mma.sync.aligned.m16n8k8.row.col.f32.tf32.tf32.f32 "
        "{%0,%1,%2,%3}, {%4,%5,%6,%7}, {%8,%9}, {%0,%1,%2,%3};"
        : "+f"(c[0]), "+f"(c[1]), "+f"(c[2]), "+f"(c[3])
        : "r"(a[0]), "r"(a[1]), "r"(a[2]), "r"(a[3]), "r"(b[0]), "r"(b[1]));
}
__device__ __forceinline__ uint32_t smem_u32(const void* p){
    uint32_t a;
    asm("{ .reg .u64 t; cvta.to.shared.u64 t, %1; cvt.u32.u64 %0, t; }" : "=r"(a) : "l"(p));
    return a;
}
__device__ __forceinline__ void cpa16(uint32_t dst, const float* src){
    asm volatile("cp.async.cg.shared.global [%0], [%1], 16;" :: "r"(dst), "l"(src) : "memory");
}
// cp.async with src-size: srcsz=0 -> zero-fill the 16B destination
__device__ __forceinline__ void cpa16z(uint32_t dst, const float* src, unsigned srcsz){
    asm volatile("cp.async.cg.shared.global [%0], [%1], 16, %2;"
                 :: "r"(dst), "l"(src), "r"(srcsz) : "memory");
}
__device__ __forceinline__ void cp_commit(){
    asm volatile("cp.async.commit_group;" ::: "memory");
}
__device__ __forceinline__ void cp_wait0(){
    asm volatile("cp.async.wait_group 0;" ::: "memory");
}

// =====================================================================
// Prep: tf32-round both weight matrices (single launch)
// =====================================================================
#define W1_N4 (CH*QKVN/4)        // 442368
#define W2_N4 (CH*CH/4)          // 147456
__global__ __launch_bounds__(256) void w_round_all(
    const float* __restrict__ w1, const float* __restrict__ w2)
{
    int i = blockIdx.x * 256 + threadIdx.x;
    if (i < W1_N4) {
        float4 v = *(const float4*)(w1 + (size_t)i * 4);
        *(float4*)(g_W1 + (size_t)i * 4) =
            make_float4(tf32r(v.x), tf32r(v.y), tf32r(v.z), tf32r(v.w));
    } else if (i < W1_N4 + W2_N4) {
        int j = i - W1_N4;
        float4 v = *(const float4*)(w2 + (size_t)j * 4);
        *(float4*)(g_W2 + (size_t)j * 4) =
            make_float4(tf32r(v.x), tf32r(v.y), tf32r(v.z), tf32r(v.w));
    }
}

// =====================================================================
// GEMM v6: as v5 (128x128 tile, 4 warps of 64x64, 2-stage cp.async,
// 1 sync/k-tile, 3 CTAs/SM), but MODE 0 stages A DIRECTLY from x/sc
// (per-thread row pointers, zfill for pad rows) — no g_XT intermediate.
// A enters HMMA as raw fp32 (tf32 subset used by HW). B pre-rounded rna.
// MODE 0: scatter g_Q/g_K/g_V.  MODE 1: A=g_AT,B=g_W2 -> out+bias.
// =====================================================================
#define AW 36
#define BW 136
#define STGW (128*AW + 32*BW)    // 8960 words
#define GSM (2*STGW*4)           // 71680 B

template<int MODE>
__global__ __launch_bounds__(128, 3)
void gemm6(const float* __restrict__ x, const float* __restrict__ sc,
           float* __restrict__ out, const float* __restrict__ bias)
{
    constexpr int NKT = CH / 32;   // 24
    extern __shared__ unsigned sm[];

    const float* B   = (MODE == 0) ? g_W1 : g_W2;
    const int    ldb = (MODE == 0) ? QKVN : CH;

    const int tid = threadIdx.x, wid = tid >> 5, lane = tid & 31;
    const int g = lane >> 2, tg = lane & 3;
    const int mt = blockIdx.y, nt = blockIdx.x;
    const int wm = (wid & 1) * 64, wn = (wid >> 1) * 64;

    const int row_a = tid >> 3, kc_a = (tid & 7) * 4;
    const int row_b = tid >> 5, nc_b = (tid & 31) * 4;
    const uint32_t sb = smem_u32(sm);

    // A source pointers per staged row (MODE 0: xt mapping; MODE 1: g_AT)
    const float* asrc[8];
    unsigned     asz[8];
    #pragma unroll
    for (int i = 0; i < 8; i++) {
        int gr = mt * 128 + row_a + i * 16;
        if (MODE == 0) {
            if (gr < MQKV) {
                int b = gr / NTOK, t = gr - b * NTOK;
                asrc[i] = (t < SEQ) ? (x + (size_t)(b * SEQ + t) * CH)
                                    : (sc + (size_t)(t - SEQ) * CH);
                asz[i] = 16u;
            } else { asrc[i] = x; asz[i] = 0u; }   // zfill
        } else {
            asrc[i] = g_AT + (size_t)gr * CH;
            asz[i] = 16u;
        }
    }

    auto issue = [&](int kt){
        const int s = kt & 1;
        const int kt0 = kt * 32;
        uint32_t ab = sb + (uint32_t)(s * STGW) * 4u;
        uint32_t bb = ab + 128u * AW * 4u;
        #pragma unroll
        for (int i = 0; i < 8; i++) {
            int r = row_a + i * 16;
            cpa16z(ab + (uint32_t)(r * AW + kc_a) * 4u,
                   asrc[i] + kt0 + kc_a, asz[i]);
        }
        #pragma unroll
        for (int i = 0; i < 8; i++) {
            int r = row_b + i * 4;
            cpa16(bb + (uint32_t)(r * BW + nc_b) * 4u,
                  B + (size_t)(kt0 + r) * ldb + nt * 128 + nc_b);
        }
        cp_commit();
    };

    float C[4][8][4];
    #pragma unroll
    for (int i = 0; i < 4; i++)
        #pragma unroll
        for (int j = 0; j < 8; j++)
            #pragma unroll
            for (int e = 0; e < 4; e++) C[i][j][e] = 0.f;

    issue(0);

    for (int kt = 0; kt < NKT; kt++) {
        cp_wait0();
        __syncthreads();
        if (kt + 1 < NKT) issue(kt + 1);

        const unsigned* As = sm + (kt & 1) * STGW;
        const unsigned* Bs = As + 128 * AW;
        #pragma unroll
        for (int ks = 0; ks < 4; ks++) {
            const int kk = ks * 8;
            unsigned a[4][4];
            #pragma unroll
            for (int mf = 0; mf < 4; mf++) {
                int r0 = wm + mf * 16 + g;
                a[mf][0] = As[(r0    ) * AW + kk + tg];
                a[mf][1] = As[(r0 + 8) * AW + kk + tg];
                a[mf][2] = As[(r0    ) * AW + kk + tg + 4];
                a[mf][3] = As[(r0 + 8) * AW + kk + tg + 4];
            }
            unsigned bf[8][2];
            #pragma unroll
            for (int nf = 0; nf < 8; nf++) {
                int c0 = wn + nf * 8 + g;
                bf[nf][0] = Bs[(kk + tg    ) * BW + c0];
                bf[nf][1] = Bs[(kk + tg + 4) * BW + c0];
            }
            #pragma unroll
            for (int mf = 0; mf < 4; mf++)
                #pragma unroll
                for (int nf = 0; nf < 8; nf++)
                    mma8(C[mf][nf], a[mf], bf[nf]);
        }
    }

    #pragma unroll
    for (int mf = 0; mf < 4; mf++) {
        #pragma unroll
        for (int nf = 0; nf < 8; nf++) {
            #pragma unroll
            for (int e = 0; e < 4; e++) {
                int r = mt * 128 + wm + mf * 16 + g + ((e >= 2) ? 8 : 0);
                int c = nt * 128 + wn + nf * 8 + tg * 2 + (e & 1);
                float v = C[mf][nf][e];
                if (MODE == 1) {
                    out[(size_t)r * CH + c] = v + bias[c];
                } else {
                    if (r >= MQKV) continue;
                    int b = r / NTOK, t = r - b * NTOK;
                    int wc = c / CH, cc = c - wc * CH;
                    int h = cc >> 6, d = cc & 63;
                    float vr = tf32r(v);
                    if (wc == 0) {
                        if (t < SEQ)
                            g_Q[((size_t)(b * HEADS + h) * SEQ + t) * DHEAD + d] = vr;
                    } else if (wc == 1) {
                        g_K[((size_t)(b * HEADS + h) * NKV + t) * DHEAD + d] = vr;
                    } else {
                        g_V[((size_t)(b * HEADS + h) * NKV + t) * DHEAD + d] = vr;
                    }
                }
            }
        }
    }
}

// =====================================================================
// Attention v5 (UNCHANGED from round 14 — proven): 256 thr / 8 warps /
// 128 q-rows per CTA, double-buffered K/V, own P buffer, 1 sync/tile.
// =====================================================================
#define KW 76
#define VW 72
#define PW 76
#define KBUF_W (64*KW)
#define VBUF_W (64*VW)
#define PBUF_W (128*PW)
#define ATT_SMEM ((2*KBUF_W + 2*VBUF_W + PBUF_W)*4)   // 114688 B

__global__ __launch_bounds__(256, 2) void attn_k()
{
    extern __shared__ unsigned smema[];
    const int bh = blockIdx.y, qt = blockIdx.x;
    const int b = bh / HEADS, h = bh - b * HEADS;
    const int tid = threadIdx.x;
    const int w = tid >> 5, lane = tid & 31;
    const int g = lane >> 2, tg = lane & 3;

    const unsigned* Qu = (const unsigned*)g_Q + (size_t)bh * SEQ * DHEAD;
    const float* Kp = g_K + (size_t)bh * NKV * DHEAD;
    const float* Vp = g_V + (size_t)bh * NKV * DHEAD;
    const uint32_t sb = smem_u32(smema);
    unsigned* Ps = smema + 2 * KBUF_W + 2 * VBUF_W;
    const int q0 = qt * 128 + w * 16;

    const int srow = tid >> 4, sc4 = (tid & 15) * 4;
    auto issue = [&](int kt){
        const int s = kt & 1;
        const int j0 = kt * 64;
        uint32_t kb = sb + (uint32_t)(s * KBUF_W) * 4u;
        uint32_t vb = sb + (uint32_t)(2 * KBUF_W + s * VBUF_W) * 4u;
        #pragma unroll
        for (int i = 0; i < 4; i++) {
            int row = srow + i * 16;
            cpa16(kb + (uint32_t)(row * KW + sc4) * 4u,
                  Kp + (size_t)(j0 + row) * DHEAD + sc4);
        }
        #pragma unroll
        for (int i = 0; i < 4; i++) {
            int row = srow + i * 16;
            cpa16(vb + (uint32_t)(row * VW + sc4) * 4u,
                  Vp + (size_t)(j0 + row) * DHEAD + sc4);
        }
        cp_commit();
    };

    unsigned aq[8][4];
    #pragma unroll
    for (int ks = 0; ks < 8; ks++) {
        aq[ks][0] = Qu[(size_t)(q0 + g    ) * DHEAD + ks * 8 + tg    ];
        aq[ks][1] = Qu[(size_t)(q0 + g + 8) * DHEAD + ks * 8 + tg    ];
        aq[ks][2] = Qu[(size_t)(q0 + g    ) * DHEAD + ks * 8 + tg + 4];
        aq[ks][3] = Qu[(size_t)(q0 + g + 8) * DHEAD + ks * 8 + tg + 4];
    }

    float O[8][4];
    #pragma unroll
    for (int i = 0; i < 8; i++)
        #pragma unroll
        for (int e = 0; e < 4; e++) O[i][e] = 0.f;
    float mrow[2] = { -1e30f, -1e30f };
    float lrow[2] = { 0.f, 0.f };

    issue(0);

    for (int kt = 0; kt < NKV / 64; kt++) {
        const int s = kt & 1;
        const int j0 = kt * 64;
        unsigned* Ks = smema + s * KBUF_W;
        unsigned* Vs = smema + 2 * KBUF_W + s * VBUF_W;

        cp_wait0();
        __syncthreads();
        if (kt + 1 < NKV / 64) issue(kt + 1);

        float S[8][4];
        #pragma unroll
        for (int i = 0; i < 8; i++)
            #pragma unroll
            for (int e = 0; e < 4; e++) S[i][e] = 0.f;
        #pragma unroll
        for (int nf = 0; nf < 8; nf++) {
            #pragma unroll
            for (int ks = 0; ks < 8; ks++) {
                unsigned bb[2];
                bb[0] = Ks[(nf * 8 + g) * KW + ks * 8 + tg    ];
                bb[1] = Ks[(nf * 8 + g) * KW + ks * 8 + tg + 4];
                mma8(S[nf], aq[ks], bb);
            }
        }

        #pragma unroll
        for (int nf = 0; nf < 8; nf++) {
            #pragma unroll
            for (int e = 0; e < 4; e++) {
                float sv = S[nf][e] * 0.125f;
                int j = j0 + nf * 8 + tg * 2 + (e & 1);
                if (j >= NTOK) sv = -1e30f;
                S[nf][e] = sv;
            }
        }
        #pragma unroll
        for (int r = 0; r < 2; r++) {
            float mx = -1e30f;
            #pragma unroll
            for (int nf = 0; nf < 8; nf++) {
                mx = fmaxf(mx, S[nf][2 * r]);
                mx = fmaxf(mx, S[nf][2 * r + 1]);
            }
            mx = fmaxf(mx, __shfl_xor_sync(0xffffffffu, mx, 1));
            mx = fmaxf(mx, __shfl_xor_sync(0xffffffffu, mx, 2));
            float mnew = fmaxf(mrow[r], mx);
            float alpha = __expf(mrow[r] - mnew);
            float sum = 0.f;
            #pragma unroll
            for (int nf = 0; nf < 8; nf++) {
                float p0 = __expf(S[nf][2 * r    ] - mnew);
                float p1 = __expf(S[nf][2 * r + 1] - mnew);
                S[nf][2 * r] = p0; S[nf][2 * r + 1] = p1;
                sum += p0 + p1;
            }
            sum += __shfl_xor_sync(0xffffffffu, sum, 1);
            sum += __shfl_xor_sync(0xffffffffu, sum, 2);
            lrow[r] = lrow[r] * alpha + sum;
            mrow[r] = mnew;
            #pragma unroll
            for (int nf = 0; nf < 8; nf++) {
                O[nf][2 * r] *= alpha; O[nf][2 * r + 1] *= alpha;
            }
        }
        #pragma unroll
        for (int nf = 0; nf < 8; nf++) {
            Ps[(w * 16 + g    ) * PW + nf * 8 + tg * 2    ] = f2t(S[nf][0]);
            Ps[(w * 16 + g    ) * PW + nf * 8 + tg * 2 + 1] = f2t(S[nf][1]);
            Ps[(w * 16 + g + 8) * PW + nf * 8 + tg * 2    ] = f2t(S[nf][2]);
            Ps[(w * 16 + g + 8) * PW + nf * 8 + tg * 2 + 1] = f2t(S[nf][3]);
        }
        __syncwarp();
        #pragma unroll
        for (int ks = 0; ks < 8; ks++) {
            unsigned ap[4];
            ap[0] = Ps[(w * 16 + g    ) * PW + ks * 8 + tg    ];
            ap[1] = Ps[(w * 16 + g + 8) * PW + ks * 8 + tg    ];
            ap[2] = Ps[(w * 16 + g    ) * PW + ks * 8 + tg + 4];
            ap[3] = Ps[(w * 16 + g + 8) * PW + ks * 8 + tg + 4];
            #pragma unroll
            for (int nf = 0; nf < 8; nf++) {
                unsigned bb[2];
                bb[0] = Vs[(ks * 8 + tg    ) * VW + nf * 8 + g];
                bb[1] = Vs[(ks * 8 + tg + 4) * VW + nf * 8 + g];
                mma8(O[nf], ap, bb);
            }
        }
    }
    float inv0 = 1.f / lrow[0], inv1 = 1.f / lrow[1];
    int row0 = b * SEQ + qt * 128 + w * 16 + g;
    #pragma unroll
    for (int nf = 0; nf < 8; nf++) {
        int col = h * DHEAD + nf * 8 + tg * 2;
        g_AT[(size_t)row0 * CH + col    ] = tf32r(O[nf][0] * inv0);
        g_AT[(size_t)row0 * CH + col + 1] = tf32r(O[nf][1] * inv0);
        g_AT[(size_t)(row0 + 8) * CH + col    ] = tf32r(O[nf][2] * inv1);
        g_AT[(size_t)(row0 + 8) * CH + col + 1] = tf32r(O[nf][3] * inv1);
    }
}

// =====================================================================
extern "C" void kernel_launch(void* const* d_in, const int* in_sizes, int n_in,
                              void* d_out, int out_size)
{
    const float* x     = (const float*)d_in[0];
    const float* sc    = (const float*)d_in[1];
    const float* Wqkv  = (const float*)d_in[2];
    const float* Wproj = (const float*)d_in[3];
    const float* bproj = (const float*)d_in[4];
    float* out = (float*)d_out;

    cudaFuncSetAttribute(gemm6<0>, cudaFuncAttributeMaxDynamicSharedMemorySize, GSM);
    cudaFuncSetAttribute(gemm6<1>, cudaFuncAttributeMaxDynamicSharedMemorySize, GSM);
    cudaFuncSetAttribute(attn_k,   cudaFuncAttributeMaxDynamicSharedMemorySize, ATT_SMEM);

    // single prep launch: round both weight matrices
    w_round_all<<<(W1_N4 + W2_N4 + 255) / 256, 256>>>(Wqkv, Wproj);

    // qkv: A streamed directly from x/sc. M=19584 (153 m-tiles), N=2304 (18)
    gemm6<0><<<dim3(18, 153), 128, GSM>>>(x, sc, nullptr, nullptr);
    // attention: 8 q-tiles x 192 (b,h), 128 q-rows per CTA
    attn_k<<<dim3(8, 192), 256, ATT_SMEM>>>();
    // proj: M=16384 (128 m-tiles), N=768 (6 n-tiles)
    gemm6<1><<<dim3(6, 128), 128, GSM>>>(nullptr, nullptr, out, bproj);
}

// round 17
// speedup vs baseline: 1.0454x; 1.0454x over previous
#include <cuda_runtime.h>
#include <cstdint>

#define BATCH 16
#define SEQ   1024
#define CH    768
#define HEADS 12
#define DHEAD 64
#define NTOK  1220              // 1024 + 196
#define NKV   1280              // padded key count
#define MQKV  (BATCH*NTOK)      // 19520 rows of xt
#define MPAD  19584             // 153*128
#define QKVN  (3*CH)            // 2304

// ---------------- scratch (zero-initialized). RULE: referenced ONLY in
// device code, never passed as kernel arguments. ----------------------------
__device__ float g_XT[MPAD*CH];                  // xt, tf32-rounded; pad rows 0
__device__ float g_W1[CH*QKVN];                  // W_qkv, tf32-rounded
__device__ float g_W2[CH*CH];                    // W_proj, tf32-rounded
__device__ float g_Q [BATCH*HEADS*SEQ *DHEAD];   // tf32-rounded
__device__ float g_K [BATCH*HEADS*NKV *DHEAD];   // tf32-rounded; pad rows 0
__device__ float g_V [BATCH*HEADS*NKV *DHEAD];   // tf32-rounded
__device__ float g_AT[BATCH*SEQ*CH];             // attn out, tf32-rounded

// ---------------- helpers ----------------
__device__ __forceinline__ unsigned f2t(float x){
    unsigned u; asm("cvt.rna.tf32.f32 %0, %1;" : "=r"(u) : "f"(x)); return u;
}
__device__ __forceinline__ float tf32r(float x){
    unsigned u; asm("cvt.rna.tf32.f32 %0, %1;" : "=r"(u) : "f"(x));
    return __uint_as_float(u);
}
__device__ __forceinline__ void mma8(float* c, const unsigned* a, const unsigned* b){
    asm volatile("mma.sync.aligned.m16n8k8.row.col.f32.tf32.tf32.f32 "
        "{%0,%1,%2,%3}, {%4,%5,%6,%7}, {%8,%9}, {%0,%1,%2,%3};"
        : "+f"(c[0]), "+f"(c[1]), "+f"(c[2]), "+f"(c[3])
        : "r"(a[0]), "r"(a[1]), "r"(a[2]), "r"(a[3]), "r"(b[0]), "r"(b[1]));
}
__device__ __forceinline__ uint32_t smem_u32(const void* p){
    uint32_t a;
    asm("{ .reg .u64 t; cvta.to.shared.u64 t, %1; cvt.u32.u64 %0, t; }" : "=r"(a) : "l"(p));
    return a;
}
__device__ __forceinline__ void cpa16(uint32_t dst, const float* src){
    asm volatile("cp.async.cg.shared.global [%0], [%1], 16;" :: "r"(dst), "l"(src) : "memory");
}
__device__ __forceinline__ void cp_commit(){
    asm volatile("cp.async.commit_group;" ::: "memory");
}
__device__ __forceinline__ void cp_wait0(){
    asm volatile("cp.async.wait_group 0;" ::: "memory");
}

// =====================================================================
// Prep A: materialize xt rows, tf32-rounded (round-14 proven)
// =====================================================================
__global__ __launch_bounds__(256) void xt_copy(
    const float* __restrict__ x, const float* __restrict__ sc)
{
    size_t i = (size_t)blockIdx.x * blockDim.x + threadIdx.x;
    size_t tot = (size_t)MQKV * (CH/4);
    if (i >= tot) return;
    int row = (int)(i / (CH/4));
    int c4  = (int)(i % (CH/4)) * 4;
    int b = row / NTOK, t = row - b * NTOK;
    const float* src = (t < SEQ) ? (x + (size_t)(b * SEQ + t) * CH)
                                 : (sc + (size_t)(t - SEQ) * CH);
    float4 v = *(const float4*)(src + c4);
    *(float4*)(g_XT + (size_t)row * CH + c4) =
        make_float4(tf32r(v.x), tf32r(v.y), tf32r(v.z), tf32r(v.w));
}

// =====================================================================
// Prep B: tf32-round both weight matrices, single launch
// =====================================================================
#define W1_N4 (CH*QKVN/4)        // 442368
#define W2_N4 (CH*CH/4)          // 147456
__global__ __launch_bounds__(256) void w_round_all(
    const float* __restrict__ w1, const float* __restrict__ w2)
{
    int i = blockIdx.x * 256 + threadIdx.x;
    if (i < W1_N4) {
        float4 v = *(const float4*)(w1 + (size_t)i * 4);
        *(float4*)(g_W1 + (size_t)i * 4) =
            make_float4(tf32r(v.x), tf32r(v.y), tf32r(v.z), tf32r(v.w));
    } else if (i < W1_N4 + W2_N4) {
        int j = i - W1_N4;
        float4 v = *(const float4*)(w2 + (size_t)j * 4);
        *(float4*)(g_W2 + (size_t)j * 4) =
            make_float4(tf32r(v.x), tf32r(v.y), tf32r(v.z), tf32r(v.w));
    }
}

// =====================================================================
// GEMM v5 (round-14 proven, byte-identical): 128x128 block tile,
// 4 warps of 64x64, 2-stage cp.async, 1 sync/k-tile, 3 CTAs/SM.
// =====================================================================
#define AW 36
#define BW 136
#define STGW (128*AW + 32*BW)    // 8960 words
#define GSM (2*STGW*4)           // 71680 B

template<int MODE>
__global__ __launch_bounds__(128, 3)
void gemm5(float* __restrict__ out, const float* __restrict__ bias)
{
    constexpr int NKT = CH / 32;   // 24
    extern __shared__ unsigned sm[];

    const float* A   = (MODE == 0) ? g_XT : g_AT;
    const float* B   = (MODE == 0) ? g_W1 : g_W2;
    const int    ldb = (MODE == 0) ? QKVN : CH;

    const int tid = threadIdx.x, wid = tid >> 5, lane = tid & 31;
    const int g = lane >> 2, tg = lane & 3;
    const int mt = blockIdx.y, nt = blockIdx.x;
    const int wm = (wid & 1) * 64, wn = (wid >> 1) * 64;

    const int row_a = tid >> 3, kc_a = (tid & 7) * 4;
    const int row_b = tid >> 5, nc_b = (tid & 31) * 4;
    const uint32_t sb = smem_u32(sm);

    auto issue = [&](int kt){
        const int s = kt & 1;
        const int kt0 = kt * 32;
        uint32_t ab = sb + (uint32_t)(s * STGW) * 4u;
        uint32_t bb = ab + 128u * AW * 4u;
        #pragma unroll
        for (int i = 0; i < 8; i++) {
            int r = row_a + i * 16;
            cpa16(ab + (uint32_t)(r * AW + kc_a) * 4u,
                  A + (size_t)(mt * 128 + r) * CH + kt0 + kc_a);
        }
        #pragma unroll
        for (int i = 0; i < 8; i++) {
            int r = row_b + i * 4;
            cpa16(bb + (uint32_t)(r * BW + nc_b) * 4u,
                  B + (size_t)(kt0 + r) * ldb + nt * 128 + nc_b);
        }
        cp_commit();
    };

    float C[4][8][4];
    #pragma unroll
    for (int i = 0; i < 4; i++)
        #pragma unroll
        for (int j = 0; j < 8; j++)
            #pragma unroll
            for (int e = 0; e < 4; e++) C[i][j][e] = 0.f;

    issue(0);

    for (int kt = 0; kt < NKT; kt++) {
        cp_wait0();
        __syncthreads();
        if (kt + 1 < NKT) issue(kt + 1);

        const unsigned* As = sm + (kt & 1) * STGW;
        const unsigned* Bs = As + 128 * AW;
        #pragma unroll
        for (int ks = 0; ks < 4; ks++) {
            const int kk = ks * 8;
            unsigned a[4][4];
            #pragma unroll
            for (int mf = 0; mf < 4; mf++) {
                int r0 = wm + mf * 16 + g;
                a[mf][0] = As[(r0    ) * AW + kk + tg];
                a[mf][1] = As[(r0 + 8) * AW + kk + tg];
                a[mf][2] = As[(r0    ) * AW + kk + tg + 4];
                a[mf][3] = As[(r0 + 8) * AW + kk + tg + 4];
            }
            unsigned bf[8][2];
            #pragma unroll
            for (int nf = 0; nf < 8; nf++) {
                int c0 = wn + nf * 8 + g;
                bf[nf][0] = Bs[(kk + tg    ) * BW + c0];
                bf[nf][1] = Bs[(kk + tg + 4) * BW + c0];
            }
            #pragma unroll
            for (int mf = 0; mf < 4; mf++)
                #pragma unroll
                for (int nf = 0; nf < 8; nf++)
                    mma8(C[mf][nf], a[mf], bf[nf]);
        }
    }

    #pragma unroll
    for (int mf = 0; mf < 4; mf++) {
        #pragma unroll
        for (int nf = 0; nf < 8; nf++) {
            #pragma unroll
            for (int e = 0; e < 4; e++) {
                int r = mt * 128 + wm + mf * 16 + g + ((e >= 2) ? 8 : 0);
                int c = nt * 128 + wn + nf * 8 + tg * 2 + (e & 1);
                float v = C[mf][nf][e];
                if (MODE == 1) {
                    out[(size_t)r * CH + c] = v + bias[c];
                } else {
                    if (r >= MQKV) continue;
                    int b = r / NTOK, t = r - b * NTOK;
                    int wc = c / CH, cc = c - wc * CH;
                    int h = cc >> 6, d = cc & 63;
                    float vr = tf32r(v);
                    if (wc == 0) {
                        if (t < SEQ)
                            g_Q[((size_t)(b * HEADS + h) * SEQ + t) * DHEAD + d] = vr;
                    } else if (wc == 1) {
                        g_K[((size_t)(b * HEADS + h) * NKV + t) * DHEAD + d] = vr;
                    } else {
                        g_V[((size_t)(b * HEADS + h) * NKV + t) * DHEAD + d] = vr;
                    }
                }
            }
        }
    }
}

// =====================================================================
// Attention v6: round-14 structure (256 thr / 128 q-rows / own P buffer /
// 1 sync per tile) + (a) log2-domain softmax: scale folded into
// 0.125*log2(e), exp2f = bare MUFU.EX2; (b) mask hoisted — only the
// last kv-tile evaluates the j>=NTOK predicate.
// =====================================================================
#define KW 76
#define VW 72
#define PW 76
#define KBUF_W (64*KW)
#define VBUF_W (64*VW)
#define PBUF_W (128*PW)
#define ATT_SMEM ((2*KBUF_W + 2*VBUF_W + PBUF_W)*4)   // 114688 B
#define SCALE_LOG2 0.1803368801111204f                // 0.125 * log2(e)

__global__ __launch_bounds__(256, 2) void attn_k()
{
    extern __shared__ unsigned smema[];
    const int bh = blockIdx.y, qt = blockIdx.x;
    const int b = bh / HEADS, h = bh - b * HEADS;
    const int tid = threadIdx.x;
    const int w = tid >> 5, lane = tid & 31;
    const int g = lane >> 2, tg = lane & 3;

    const unsigned* Qu = (const unsigned*)g_Q + (size_t)bh * SEQ * DHEAD;
    const float* Kp = g_K + (size_t)bh * NKV * DHEAD;
    const float* Vp = g_V + (size_t)bh * NKV * DHEAD;
    const uint32_t sb = smem_u32(smema);
    unsigned* Ps = smema + 2 * KBUF_W + 2 * VBUF_W;
    const int q0 = qt * 128 + w * 16;

    const int srow = tid >> 4, sc4 = (tid & 15) * 4;
    auto issue = [&](int kt){
        const int s = kt & 1;
        const int j0 = kt * 64;
        uint32_t kb = sb + (uint32_t)(s * KBUF_W) * 4u;
        uint32_t vb = sb + (uint32_t)(2 * KBUF_W + s * VBUF_W) * 4u;
        #pragma unroll
        for (int i = 0; i < 4; i++) {
            int row = srow + i * 16;
            cpa16(kb + (uint32_t)(row * KW + sc4) * 4u,
                  Kp + (size_t)(j0 + row) * DHEAD + sc4);
        }
        #pragma unroll
        for (int i = 0; i < 4; i++) {
            int row = srow + i * 16;
            cpa16(vb + (uint32_t)(row * VW + sc4) * 4u,
                  Vp + (size_t)(j0 + row) * DHEAD + sc4);
        }
        cp_commit();
    };

    unsigned aq[8][4];
    #pragma unroll
    for (int ks = 0; ks < 8; ks++) {
        aq[ks][0] = Qu[(size_t)(q0 + g    ) * DHEAD + ks * 8 + tg    ];
        aq[ks][1] = Qu[(size_t)(q0 + g + 8) * DHEAD + ks * 8 + tg    ];
        aq[ks][2] = Qu[(size_t)(q0 + g    ) * DHEAD + ks * 8 + tg + 4];
        aq[ks][3] = Qu[(size_t)(q0 + g + 8) * DHEAD + ks * 8 + tg + 4];
    }

    float O[8][4];
    #pragma unroll
    for (int i = 0; i < 8; i++)
        #pragma unroll
        for (int e = 0; e < 4; e++) O[i][e] = 0.f;
    float mrow[2] = { -1e30f, -1e30f };   // log2-domain running max
    float lrow[2] = { 0.f, 0.f };

    issue(0);

    for (int kt = 0; kt < NKV / 64; kt++) {
        const int s = kt & 1;
        const int j0 = kt * 64;
        unsigned* Ks = smema + s * KBUF_W;
        unsigned* Vs = smema + 2 * KBUF_W + s * VBUF_W;

        cp_wait0();
        __syncthreads();
        if (kt + 1 < NKV / 64) issue(kt + 1);

        // ---- S = Q @ K^T ----
        float S[8][4];
        #pragma unroll
        for (int i = 0; i < 8; i++)
            #pragma unroll
            for (int e = 0; e < 4; e++) S[i][e] = 0.f;
        #pragma unroll
        for (int nf = 0; nf < 8; nf++) {
            #pragma unroll
            for (int ks = 0; ks < 8; ks++) {
                unsigned bb[2];
                bb[0] = Ks[(nf * 8 + g) * KW + ks * 8 + tg    ];
                bb[1] = Ks[(nf * 8 + g) * KW + ks * 8 + tg + 4];
                mma8(S[nf], aq[ks], bb);
            }
        }

        // ---- scale into log2 domain; mask only on the final tile ----
        if (j0 + 63 >= NTOK) {
            #pragma unroll
            for (int nf = 0; nf < 8; nf++) {
                #pragma unroll
                for (int e = 0; e < 4; e++) {
                    float sv = S[nf][e] * SCALE_LOG2;
                    int j = j0 + nf * 8 + tg * 2 + (e & 1);
                    if (j >= NTOK) sv = -1e30f;
                    S[nf][e] = sv;
                }
            }
        } else {
            #pragma unroll
            for (int nf = 0; nf < 8; nf++) {
                #pragma unroll
                for (int e = 0; e < 4; e++)
                    S[nf][e] *= SCALE_LOG2;
            }
        }
        // ---- online softmax (log2 domain; exp2f = MUFU.EX2) ----
        #pragma unroll
        for (int r = 0; r < 2; r++) {
            float mx = -1e30f;
            #pragma unroll
            for (int nf = 0; nf < 8; nf++) {
                mx = fmaxf(mx, S[nf][2 * r]);
                mx = fmaxf(mx, S[nf][2 * r + 1]);
            }
            mx = fmaxf(mx, __shfl_xor_sync(0xffffffffu, mx, 1));
            mx = fmaxf(mx, __shfl_xor_sync(0xffffffffu, mx, 2));
            float mnew = fmaxf(mrow[r], mx);
            float alpha = exp2f(mrow[r] - mnew);
            float sum = 0.f;
            #pragma unroll
            for (int nf = 0; nf < 8; nf++) {
                float p0 = exp2f(S[nf][2 * r    ] - mnew);
                float p1 = exp2f(S[nf][2 * r + 1] - mnew);
                S[nf][2 * r] = p0; S[nf][2 * r + 1] = p1;
                sum += p0 + p1;
            }
            sum += __shfl_xor_sync(0xffffffffu, sum, 1);
            sum += __shfl_xor_sync(0xffffffffu, sum, 2);
            lrow[r] = lrow[r] * alpha + sum;
            mrow[r] = mnew;
            #pragma unroll
            for (int nf = 0; nf < 8; nf++) {
                O[nf][2 * r] *= alpha; O[nf][2 * r + 1] *= alpha;
            }
        }
        // ---- store P (warp-private rows of own buffer) ----
        #pragma unroll
        for (int nf = 0; nf < 8; nf++) {
            Ps[(w * 16 + g    ) * PW + nf * 8 + tg * 2    ] = f2t(S[nf][0]);
            Ps[(w * 16 + g    ) * PW + nf * 8 + tg * 2 + 1] = f2t(S[nf][1]);
            Ps[(w * 16 + g + 8) * PW + nf * 8 + tg * 2    ] = f2t(S[nf][2]);
            Ps[(w * 16 + g + 8) * PW + nf * 8 + tg * 2 + 1] = f2t(S[nf][3]);
        }
        __syncwarp();
        // ---- O += P @ V ----
        #pragma unroll
        for (int ks = 0; ks < 8; ks++) {
            unsigned ap[4];
            ap[0] = Ps[(w * 16 + g    ) * PW + ks * 8 + tg    ];
            ap[1] = Ps[(w * 16 + g + 8) * PW + ks * 8 + tg    ];
            ap[2] = Ps[(w * 16 + g    ) * PW + ks * 8 + tg + 4];
            ap[3] = Ps[(w * 16 + g + 8) * PW + ks * 8 + tg + 4];
            #pragma unroll
            for (int nf = 0; nf < 8; nf++) {
                unsigned bb[2];
                bb[0] = Vs[(ks * 8 + tg    ) * VW + nf * 8 + g];
                bb[1] = Vs[(ks * 8 + tg + 4) * VW + nf * 8 + g];
                mma8(O[nf], ap, bb);
            }
        }
        // no end barrier: next iteration's top barrier closes these reads
    }
    float inv0 = 1.f / lrow[0], inv1 = 1.f / lrow[1];
    int row0 = b * SEQ + qt * 128 + w * 16 + g;
    #pragma unroll
    for (int nf = 0; nf < 8; nf++) {
        int col = h * DHEAD + nf * 8 + tg * 2;
        g_AT[(size_t)row0 * CH + col    ] = tf32r(O[nf][0] * inv0);
        g_AT[(size_t)row0 * CH + col + 1] = tf32r(O[nf][1] * inv0);
        g_AT[(size_t)(row0 + 8) * CH + col    ] = tf32r(O[nf][2] * inv1);
        g_AT[(size_t)(row0 + 8) * CH + col + 1] = tf32r(O[nf][3] * inv1);
    }
}

// =====================================================================
extern "C" void kernel_launch(void* const* d_in, const int* in_sizes, int n_in,
                              void* d_out, int out_size)
{
    const float* x     = (const float*)d_in[0];
    const float* sc    = (const float*)d_in[1];
    const float* Wqkv  = (const float*)d_in[2];
    const float* Wproj = (const float*)d_in[3];
    const float* bproj = (const float*)d_in[4];
    float* out = (float*)d_out;

    cudaFuncSetAttribute(gemm5<0>, cudaFuncAttributeMaxDynamicSharedMemorySize, GSM);
    cudaFuncSetAttribute(gemm5<1>, cudaFuncAttributeMaxDynamicSharedMemorySize, GSM);
    cudaFuncSetAttribute(attn_k,   cudaFuncAttributeMaxDynamicSharedMemorySize, ATT_SMEM);

    {
        size_t tot = (size_t)MQKV * (CH / 4);
        xt_copy<<<(unsigned)((tot + 255) / 256), 256>>>(x, sc);
    }
    w_round_all<<<(W1_N4 + W2_N4 + 255) / 256, 256>>>(Wqkv, Wproj);

    // qkv: M=19584 (153 m-tiles), N=2304 (18 n-tiles)
    gemm5<0><<<dim3(18, 153), 128, GSM>>>(nullptr, nullptr);
    // attention: 8 q-tiles x 192 (b,h), 128 q-rows per CTA
    attn_k<<<dim3(8, 192), 256, ATT_SMEM>>>();
    // proj: M=16384 (128 m-tiles), N=768 (6 n-tiles)
    gemm5<1><<<dim3(6, 128), 128, GSM>>>(out, bproj);
}